// round 7
// baseline (speedup 1.0000x reference)
#include <cuda_runtime.h>
#include <cuda_fp16.h>
#include <cstdint>

#define MAXN 50000
#define MAXE 800000
#define FIN 256
#define FH  64
#define FOUT 40
#define KSTEPS 10
#define SCAN_TPB 256
#define MAXBLK 256

// packed fp32x2 helpers (Blackwell dual fp32)
#define PACK2(out, lo, hi) asm("mov.b64 %0, {%1, %2};" : "=l"(out) : "f"(lo), "f"(hi))
#define UNPACK2(lo, hi, in) asm("mov.b64 {%0, %1}, %2;" : "=f"(lo), "=f"(hi) : "l"(in))
#define FMA2(d, a, b, c) asm("fma.rn.f32x2 %0, %1, %2, %3;" : "=l"(d) : "l"(a), "l"(b), "l"(c))

// ---------------- static device scratch ----------------
__device__ int     g_deg[MAXN];
__device__ float   g_dinv[MAXN];
__device__ int     g_ptr[MAXN + 1];
__device__ int     g_cursor[MAXN];
__device__ int     g_part[MAXBLK];
__device__ __align__(16) int2    g_csr[MAXE];
// feature pairing: slot p of a node = features (2p, 2p+1)
__device__ __align__(16) float2  g_h0[MAXN * 32];
__device__ __align__(16) __half2 g_hA[MAXN * 32];
__device__ __align__(16) __half2 g_hB[MAXN * 32];
__device__ __align__(16) float   g_mlp1[MAXN * FH];

__device__ __forceinline__ int clampN(int v, int n) {
    v = v < 0 ? 0 : v;
    return v >= n ? n - 1 : v;
}

// ---------------- graph preprocessing ----------------
__global__ void init_kernel(int n) {
    int i = blockIdx.x * blockDim.x + threadIdx.x;
    if (i < n) { g_deg[i] = 1; g_cursor[i] = 0; }   // self loop
}

__global__ void hist_kernel(const int* __restrict__ ei, int E, int n) {
    int e = blockIdx.x * blockDim.x + threadIdx.x;
    if (e < E) atomicAdd(&g_deg[clampN(ei[E + e], n)], 1);
}

// scan stage A: per-block sums of (deg-1); also computes dinv
__global__ void scanA_kernel(int n) {
    int i = blockIdx.x * blockDim.x + threadIdx.x;
    int lane = threadIdx.x & 31, wid = threadIdx.x >> 5;
    __shared__ int ws[SCAN_TPB / 32];
    int d = (i < n) ? g_deg[i] : 1;
    if (i < n) g_dinv[i] = rsqrtf((float)d);
    int v = (i < n) ? (d - 1) : 0;
    #pragma unroll
    for (int o = 16; o > 0; o >>= 1) v += __shfl_down_sync(0xFFFFFFFFu, v, o);
    if (lane == 0) ws[wid] = v;
    __syncthreads();
    if (wid == 0) {
        int s = (lane < SCAN_TPB / 32) ? ws[lane] : 0;
        #pragma unroll
        for (int o = 16; o > 0; o >>= 1) s += __shfl_down_sync(0xFFFFFFFFu, s, o);
        if (lane == 0) g_part[blockIdx.x] = s;
    }
}

// scan stage B: exclusive scan of block partials (single block)
__global__ void scanB_kernel(int nblocks, int n) {
    int tid = threadIdx.x, lane = tid & 31, wid = tid >> 5;
    __shared__ int ws[8];
    int v = (tid < nblocks) ? g_part[tid] : 0;
    int x = v;
    #pragma unroll
    for (int o = 1; o < 32; o <<= 1) {
        int y = __shfl_up_sync(0xFFFFFFFFu, x, o);
        if (lane >= o) x += y;
    }
    if (lane == 31) ws[wid] = x;
    __syncthreads();
    if (wid == 0) {
        int s = (lane < 8) ? ws[lane] : 0;
        #pragma unroll
        for (int o = 1; o < 8; o <<= 1) {
            int y = __shfl_up_sync(0xFFFFFFFFu, s, o);
            if (lane >= o) s += y;
        }
        ws[lane] = s;
    }
    __syncthreads();
    int incl = x + (wid > 0 ? ws[wid - 1] : 0);
    if (tid < nblocks) g_part[tid] = incl - v;
    if (tid == nblocks - 1) g_ptr[n] = incl;
}

// scan stage C: intra-block exclusive scan + block offset -> g_ptr
__global__ void scanC_kernel(int n) {
    int i = blockIdx.x * blockDim.x + threadIdx.x;
    int lane = threadIdx.x & 31, wid = threadIdx.x >> 5;
    __shared__ int ws[SCAN_TPB / 32];
    int v = (i < n) ? (g_deg[i] - 1) : 0;
    int x = v;
    #pragma unroll
    for (int o = 1; o < 32; o <<= 1) {
        int y = __shfl_up_sync(0xFFFFFFFFu, x, o);
        if (lane >= o) x += y;
    }
    if (lane == 31) ws[wid] = x;
    __syncthreads();
    if (wid == 0) {
        int s = (lane < SCAN_TPB / 32) ? ws[lane] : 0;
        #pragma unroll
        for (int o = 1; o < SCAN_TPB / 32; o <<= 1) {
            int y = __shfl_up_sync(0xFFFFFFFFu, s, o);
            if (lane >= o) s += y;
        }
        ws[lane] = s;
    }
    __syncthreads();
    int incl = x + (wid > 0 ? ws[wid - 1] : 0);
    if (i < n) g_ptr[i] = incl - v + g_part[blockIdx.x];
}

__global__ void scatter_kernel(const int* __restrict__ ei, int E, int n) {
    int e = blockIdx.x * blockDim.x + threadIdx.x;
    if (e < E) {
        int r = clampN(ei[e], n);
        int c = clampN(ei[E + e], n);
        int pos = g_ptr[c] + atomicAdd(&g_cursor[c], 1);
        float w = g_dinv[r] * g_dinv[c];
        g_csr[pos] = make_int2(r, __float_as_int(w));
    }
}

// ---------------- MLP encode: warp/node, lane owns features (2l, 2l+1), f32x2 ----
__global__ void mlp1_kernel(const float* __restrict__ x,
                            const float* __restrict__ W1,
                            const float* __restrict__ b1, int n) {
    int warp = (blockIdx.x * blockDim.x + threadIdx.x) >> 5;
    int lane = threadIdx.x & 31;
    if (warp >= n) return;
    const float* xr = x + (size_t)warp * FIN;
    unsigned long long acc;
    PACK2(acc, b1[2 * lane], b1[2 * lane + 1]);
    for (int kb = 0; kb < FIN; kb += 32) {
        float xv = xr[kb + lane];
        #pragma unroll
        for (int j = 0; j < 32; j++) {
            float xk = __shfl_sync(0xFFFFFFFFu, xv, j);
            unsigned long long xk2, wv;
            PACK2(xk2, xk, xk);
            wv = *(const unsigned long long*)&W1[(kb + j) * FH + 2 * lane];
            FMA2(acc, xk2, wv, acc);
        }
    }
    float a0, a1;
    UNPACK2(a0, a1, acc);
    *(float2*)&g_mlp1[warp * FH + 2 * lane] =
        make_float2(fmaxf(a0, 0.0f), fmaxf(a1, 0.0f));
}

__global__ void mlp2_kernel(const float* __restrict__ W2,
                            const float* __restrict__ b2, int n) {
    int warp = (blockIdx.x * blockDim.x + threadIdx.x) >> 5;
    int lane = threadIdx.x & 31;
    if (warp >= n) return;
    const float* hr = g_mlp1 + (size_t)warp * FH;
    unsigned long long acc;
    PACK2(acc, b2[2 * lane], b2[2 * lane + 1]);
    #pragma unroll
    for (int kb = 0; kb < FH; kb += 32) {
        float hv = hr[kb + lane];
        #pragma unroll
        for (int j = 0; j < 32; j++) {
            float hk = __shfl_sync(0xFFFFFFFFu, hv, j);
            unsigned long long hk2, wv;
            PACK2(hk2, hk, hk);
            wv = *(const unsigned long long*)&W2[(kb + j) * FH + 2 * lane];
            FMA2(acc, hk2, wv, acc);
        }
    }
    float a0, a1;
    UNPACK2(a0, a1, acc);
    g_hA[warp * 32 + lane] = __floats2half2_rn(a0, a1);   // features (2l, 2l+1)
    g_h0[warp * 32 + lane] = make_float2(a0, a1);
}

// ---------------- APPNP step: TWO nodes per warp, interleaved edge loops -------
template <int SRC_A, int DECODE>
__global__ void prop_kernel(const float* __restrict__ Wf,
                            const float* __restrict__ bf,
                            float* __restrict__ out, int n) {
    int pair = (blockIdx.x * blockDim.x + threadIdx.x) >> 5;
    int lane = threadIdx.x & 31;
    int node0 = pair * 2;
    if (node0 >= n) return;
    int node1 = node0 + 1;
    int has1 = (node1 < n);

    const __half2* __restrict__ hin  = SRC_A ? g_hA : g_hB;
    __half2*       __restrict__ hout = SRC_A ? g_hB : g_hA;

    int2 p01 = *(const int2*)&g_ptr[node0];   // (ptr[node0], ptr[node0+1])
    int s0 = p01.x, e0end = p01.y;
    int s1 = e0end, e1end = has1 ? g_ptr[node0 + 2] : e0end;

    float d0 = g_dinv[node0];
    float2 hv0 = __half22float2(hin[node0 * 32 + lane]);
    float ax0 = d0 * d0 * hv0.x;
    float ay0 = d0 * d0 * hv0.y;

    float ax1 = 0.0f, ay1 = 0.0f;
    if (has1) {
        float d1 = g_dinv[node1];
        float2 hv1 = __half22float2(hin[node1 * 32 + lane]);
        ax1 = d1 * d1 * hv1.x;
        ay1 = d1 * d1 * hv1.y;
    }

    int e0 = s0, e1 = s1;
    // joint interleaved loop: 2 edges per node per iteration (4 independent gathers)
    while (e0 + 2 <= e0end && e1 + 2 <= e1end) {
        int2 a0 = g_csr[e0 + 0];
        int2 a1 = g_csr[e0 + 1];
        int2 b0 = g_csr[e1 + 0];
        int2 b1 = g_csr[e1 + 1];
        __half2 va0 = hin[a0.x * 32 + lane];
        __half2 va1 = hin[a1.x * 32 + lane];
        __half2 vb0 = hin[b0.x * 32 + lane];
        __half2 vb1 = hin[b1.x * 32 + lane];
        float2 fa0 = __half22float2(va0);
        float2 fa1 = __half22float2(va1);
        float2 fb0 = __half22float2(vb0);
        float2 fb1 = __half22float2(vb1);
        float wa0 = __int_as_float(a0.y);
        float wa1 = __int_as_float(a1.y);
        float wb0 = __int_as_float(b0.y);
        float wb1 = __int_as_float(b1.y);
        ax0 = fmaf(wa0, fa0.x, ax0); ay0 = fmaf(wa0, fa0.y, ay0);
        ax0 = fmaf(wa1, fa1.x, ax0); ay0 = fmaf(wa1, fa1.y, ay0);
        ax1 = fmaf(wb0, fb0.x, ax1); ay1 = fmaf(wb0, fb0.y, ay1);
        ax1 = fmaf(wb1, fb1.x, ax1); ay1 = fmaf(wb1, fb1.y, ay1);
        e0 += 2; e1 += 2;
    }
    // node0 remainder (unroll 4 + scalar)
    for (; e0 + 4 <= e0end; e0 += 4) {
        int2 c0 = g_csr[e0 + 0], c1 = g_csr[e0 + 1], c2 = g_csr[e0 + 2], c3 = g_csr[e0 + 3];
        __half2 v0 = hin[c0.x * 32 + lane], v1 = hin[c1.x * 32 + lane];
        __half2 v2 = hin[c2.x * 32 + lane], v3 = hin[c3.x * 32 + lane];
        float2 f0 = __half22float2(v0), f1 = __half22float2(v1);
        float2 f2 = __half22float2(v2), f3 = __half22float2(v3);
        float w0 = __int_as_float(c0.y), w1 = __int_as_float(c1.y);
        float w2 = __int_as_float(c2.y), w3 = __int_as_float(c3.y);
        ax0 = fmaf(w0, f0.x, ax0); ay0 = fmaf(w0, f0.y, ay0);
        ax0 = fmaf(w1, f1.x, ax0); ay0 = fmaf(w1, f1.y, ay0);
        ax0 = fmaf(w2, f2.x, ax0); ay0 = fmaf(w2, f2.y, ay0);
        ax0 = fmaf(w3, f3.x, ax0); ay0 = fmaf(w3, f3.y, ay0);
    }
    for (; e0 < e0end; e0++) {
        int2 s = g_csr[e0];
        float2 f = __half22float2(hin[s.x * 32 + lane]);
        float w = __int_as_float(s.y);
        ax0 = fmaf(w, f.x, ax0); ay0 = fmaf(w, f.y, ay0);
    }
    // node1 remainder
    for (; e1 + 4 <= e1end; e1 += 4) {
        int2 c0 = g_csr[e1 + 0], c1 = g_csr[e1 + 1], c2 = g_csr[e1 + 2], c3 = g_csr[e1 + 3];
        __half2 v0 = hin[c0.x * 32 + lane], v1 = hin[c1.x * 32 + lane];
        __half2 v2 = hin[c2.x * 32 + lane], v3 = hin[c3.x * 32 + lane];
        float2 f0 = __half22float2(v0), f1 = __half22float2(v1);
        float2 f2 = __half22float2(v2), f3 = __half22float2(v3);
        float w0 = __int_as_float(c0.y), w1 = __int_as_float(c1.y);
        float w2 = __int_as_float(c2.y), w3 = __int_as_float(c3.y);
        ax1 = fmaf(w0, f0.x, ax1); ay1 = fmaf(w0, f0.y, ay1);
        ax1 = fmaf(w1, f1.x, ax1); ay1 = fmaf(w1, f1.y, ay1);
        ax1 = fmaf(w2, f2.x, ax1); ay1 = fmaf(w2, f2.y, ay1);
        ax1 = fmaf(w3, f3.x, ax1); ay1 = fmaf(w3, f3.y, ay1);
    }
    for (; e1 < e1end; e1++) {
        int2 s = g_csr[e1];
        float2 f = __half22float2(hin[s.x * 32 + lane]);
        float w = __int_as_float(s.y);
        ax1 = fmaf(w, f.x, ax1); ay1 = fmaf(w, f.y, ay1);
    }

    float2 t0 = g_h0[node0 * 32 + lane];
    float ox0 = 0.9f * ax0 + 0.1f * t0.x;
    float oy0 = 0.9f * ay0 + 0.1f * t0.y;
    float ox1 = 0.0f, oy1 = 0.0f;
    if (has1) {
        float2 t1 = g_h0[node1 * 32 + lane];
        ox1 = 0.9f * ax1 + 0.1f * t1.x;
        oy1 = 0.9f * ay1 + 0.1f * t1.y;
    }

    if (!DECODE) {
        hout[node0 * 32 + lane] = __floats2half2_rn(ox0, oy0);
        if (has1) hout[node1 * 32 + lane] = __floats2half2_rn(ox1, oy1);
    } else {
        float bias0 = bf[lane];
        float bias1 = (lane < FOUT - 32) ? bf[lane + 32] : 0.0f;
        float acc0 = bias0, acc1 = bias1;
        float acc0b = bias0, acc1b = bias1;
        #pragma unroll
        for (int j = 0; j < 32; j++) {
            float hx0 = __shfl_sync(0xFFFFFFFFu, ox0, j);
            float hy0 = __shfl_sync(0xFFFFFFFFu, oy0, j);
            float hx1 = __shfl_sync(0xFFFFFFFFu, ox1, j);
            float hy1 = __shfl_sync(0xFFFFFFFFu, oy1, j);
            float w0 = Wf[(2 * j) * FOUT + lane];
            float w1 = Wf[(2 * j + 1) * FOUT + lane];
            acc0  = fmaf(hx0, w0, acc0);
            acc0  = fmaf(hy0, w1, acc0);
            acc0b = fmaf(hx1, w0, acc0b);
            acc0b = fmaf(hy1, w1, acc0b);
            if (lane < FOUT - 32) {
                float w2 = Wf[(2 * j) * FOUT + lane + 32];
                float w3 = Wf[(2 * j + 1) * FOUT + lane + 32];
                acc1  = fmaf(hx0, w2, acc1);
                acc1  = fmaf(hy0, w3, acc1);
                acc1b = fmaf(hx1, w2, acc1b);
                acc1b = fmaf(hy1, w3, acc1b);
            }
        }
        out[(size_t)node0 * FOUT + lane] = acc0;
        if (lane < FOUT - 32) out[(size_t)node0 * FOUT + lane + 32] = acc1;
        if (has1) {
            out[(size_t)node1 * FOUT + lane] = acc0b;
            if (lane < FOUT - 32) out[(size_t)node1 * FOUT + lane + 32] = acc1b;
        }
    }
}

// ---------------- launch ----------------
extern "C" void kernel_launch(void* const* d_in, const int* in_sizes, int n_in,
                              void* d_out, int out_size) {
    const float* x  = (const float*)d_in[0];
    const int*   ei = (const int*)d_in[1];
    const float* W1 = (const float*)d_in[2];
    const float* b1 = (const float*)d_in[3];
    const float* W2 = (const float*)d_in[4];
    const float* b2 = (const float*)d_in[5];
    const float* Wf = (const float*)d_in[6];
    const float* bf = (const float*)d_in[7];
    float* out = (float*)d_out;

    int N = in_sizes[0] / FIN;
    int E = in_sizes[1] / 2;
    if (N > MAXN) N = MAXN;
    if (E > MAXE) E = MAXE;

    int tpb = 256;
    int nblk = (N + SCAN_TPB - 1) / SCAN_TPB;

    init_kernel<<<(N + tpb - 1) / tpb, tpb>>>(N);
    hist_kernel<<<(E + tpb - 1) / tpb, tpb>>>(ei, E, N);
    scanA_kernel<<<nblk, SCAN_TPB>>>(N);          // also computes dinv
    scanB_kernel<<<1, MAXBLK>>>(nblk, N);
    scanC_kernel<<<nblk, SCAN_TPB>>>(N);
    scatter_kernel<<<(E + tpb - 1) / tpb, tpb>>>(ei, E, N);

    int wblocks = (N + 7) / 8;                 // warp-per-node kernels
    mlp1_kernel<<<wblocks, tpb>>>(x, W1, b1, N);
    mlp2_kernel<<<wblocks, tpb>>>(W2, b2, N);

    // prop: 2 nodes per warp -> half the warps
    int npairs = (N + 1) / 2;
    int pblocks = (npairs + 7) / 8;
    for (int t = 0; t < KSTEPS - 1; t++) {
        if ((t & 1) == 0) prop_kernel<1, 0><<<pblocks, tpb>>>(Wf, bf, out, N);
        else              prop_kernel<0, 0><<<pblocks, tpb>>>(Wf, bf, out, N);
    }
    prop_kernel<0, 1><<<pblocks, tpb>>>(Wf, bf, out, N);
}